// round 5
// baseline (speedup 1.0000x reference)
#include <cuda_runtime.h>
#include <cuda_bf16.h>
#include <cstdint>

// Problem constants (fixed by the dataset)
#define NNODES 50000
#define IN_F   256
#define HID_F  256
#define OUT_F  128
// out row pitch = OUT_F + HID_F + OUT_F = 512

// ---------------------------------------------------------------------------
// Scratch (no cudaMalloc allowed): device globals.
//   g_agg1 : A @ X            [N, 256]
//   g_S    : relu(X@mlp_w1+b) [N, 256]
//   g_T    : h1 @ W2          [N, 128]
// ---------------------------------------------------------------------------
__device__ float g_agg1[(size_t)NNODES * HID_F];
__device__ float g_S   [(size_t)NNODES * HID_F];
__device__ float g_T   [(size_t)NNODES * OUT_F];

// ---------------------------------------------------------------------------
// Zero-init: g_agg1 (N*256 floats) and out[:, 384:512) (N*128 floats)
// ---------------------------------------------------------------------------
__global__ __launch_bounds__(256) void zero_kernel(float4* __restrict__ agg1,
                                                   float4* __restrict__ out,
                                                   int n)
{
    int idx = blockIdx.x * blockDim.x + threadIdx.x;
    int total1 = n * 64;              // N*256 floats = N*64 float4
    if (idx < total1) {
        agg1[idx] = make_float4(0.f, 0.f, 0.f, 0.f);
    } else {
        int t = idx - total1;
        if (t < n * 32) {             // N*128 floats = N*32 float4
            int row = t >> 5;
            int c   = t & 31;
            // out pitch = 512 floats = 128 float4; col 384 = f4 offset 96
            out[(size_t)row * 128 + 96 + c] = make_float4(0.f, 0.f, 0.f, 0.f);
        }
    }
}

// ---------------------------------------------------------------------------
// Edge-parallel SpMM: out[dst] += w * x[src]
//   C4 = row width in float4 (64 for 256 cols, 32 for 128 cols).
//   x row pitch (in float4) == C4 for both call sites.
//   out row pitch given in floats (opitch).
// Uses red.global.add.v4.f32 (sm_90+) — fire-and-forget vector reduction.
// ---------------------------------------------------------------------------
template <int C4>
__global__ __launch_bounds__(256) void spmm_kernel(
    const float* __restrict__ x,
    const int*   __restrict__ src,
    const int*   __restrict__ dst,
    const float* __restrict__ w,
    int nE,
    float* __restrict__ out, int opitch)
{
    int idx = blockIdx.x * blockDim.x + threadIdx.x;
    int e = idx / C4;
    int c = idx % C4;
    if (e >= nE) return;

    int   s  = __ldg(src + e);
    int   d  = __ldg(dst + e);
    float ww = __ldg(w + e);

    float4 v = __ldg(reinterpret_cast<const float4*>(x) + (size_t)s * C4 + c);

    float* o = out + (size_t)d * opitch + c * 4;
    asm volatile("red.global.add.v4.f32 [%0], {%1, %2, %3, %4};"
                 :: "l"(o), "f"(v.x * ww), "f"(v.y * ww),
                    "f"(v.z * ww), "f"(v.w * ww)
                 : "memory");
}

// ---------------------------------------------------------------------------
// FP32 SGEMM: C[M, Ncols] = act( A[M, 256] @ B[256, Ncols] + bias )
//   BM=128, BN=128, BK=16, 256 threads, 8x8 per thread.
//   K fixed at 256. Ncols a multiple of 128 (grid.x tiles it).
//   A row pitch lda, C row pitch ldc (supports writing into out slab).
// ---------------------------------------------------------------------------
#define GEMM_K 256
#define GBM 128
#define GBN 128
#define GBK 16

__global__ __launch_bounds__(256) void sgemm_kernel(
    const float* __restrict__ A, int lda,
    const float* __restrict__ B, int ldb,
    float* __restrict__ C, int ldc,
    const float* __restrict__ bias, int do_relu, int M)
{
    __shared__ float As[GBK][GBM];
    __shared__ float Bs[GBK][GBN];

    const int tid = threadIdx.x;
    const int tr  = tid >> 4;   // 0..15  (row group)
    const int tc  = tid & 15;   // 0..15  (col group)
    const int mBase = blockIdx.y * GBM;
    const int nBase = blockIdx.x * GBN;

    float acc[8][8];
#pragma unroll
    for (int i = 0; i < 8; ++i)
#pragma unroll
        for (int j = 0; j < 8; ++j) acc[i][j] = 0.f;

    // A loader: 512 float4 per tile, 2 per thread.
    const int arow0 = tid >> 2;   // 0..63
    const int akq   = tid & 3;    // which float4 within the 16-wide k slab
    // B loader: 512 float4 per tile, 2 per thread.
    const int bk0 = tid >> 5;     // 0..7
    const int bn4 = tid & 31;     // 0..31

    for (int k0 = 0; k0 < GEMM_K; k0 += GBK) {
#pragma unroll
        for (int h = 0; h < 2; ++h) {
            int row = arow0 + h * 64;
            int gm  = mBase + row;
            float4 v = make_float4(0.f, 0.f, 0.f, 0.f);
            if (gm < M)
                v = __ldg(reinterpret_cast<const float4*>(
                        A + (size_t)gm * lda + k0 + akq * 4));
            As[akq * 4 + 0][row] = v.x;
            As[akq * 4 + 1][row] = v.y;
            As[akq * 4 + 2][row] = v.z;
            As[akq * 4 + 3][row] = v.w;
        }
#pragma unroll
        for (int h = 0; h < 2; ++h) {
            int kr = bk0 + h * 8;
            float4 v = __ldg(reinterpret_cast<const float4*>(
                    B + (size_t)(k0 + kr) * ldb + nBase + bn4 * 4));
            *reinterpret_cast<float4*>(&Bs[kr][bn4 * 4]) = v;
        }
        __syncthreads();

#pragma unroll
        for (int kk = 0; kk < GBK; ++kk) {
            float4 a0 = *reinterpret_cast<const float4*>(&As[kk][tr * 8]);
            float4 a1 = *reinterpret_cast<const float4*>(&As[kk][tr * 8 + 4]);
            float4 b0 = *reinterpret_cast<const float4*>(&Bs[kk][tc * 8]);
            float4 b1 = *reinterpret_cast<const float4*>(&Bs[kk][tc * 8 + 4]);
            float a[8] = {a0.x, a0.y, a0.z, a0.w, a1.x, a1.y, a1.z, a1.w};
            float b[8] = {b0.x, b0.y, b0.z, b0.w, b1.x, b1.y, b1.z, b1.w};
#pragma unroll
            for (int i = 0; i < 8; ++i)
#pragma unroll
                for (int j = 0; j < 8; ++j)
                    acc[i][j] = fmaf(a[i], b[j], acc[i][j]);
        }
        __syncthreads();
    }

    // Epilogue
    float bv[8];
#pragma unroll
    for (int j = 0; j < 8; ++j)
        bv[j] = bias ? __ldg(bias + nBase + tc * 8 + j) : 0.f;

#pragma unroll
    for (int i = 0; i < 8; ++i) {
        int gm = mBase + tr * 8 + i;
        if (gm < M) {
            float o[8];
#pragma unroll
            for (int j = 0; j < 8; ++j) {
                float v = acc[i][j] + bv[j];
                if (do_relu) v = fmaxf(v, 0.f);
                o[j] = v;
            }
            float* cp = C + (size_t)gm * ldc + nBase + tc * 8;
            *reinterpret_cast<float4*>(cp)     = make_float4(o[0], o[1], o[2], o[3]);
            *reinterpret_cast<float4*>(cp + 4) = make_float4(o[4], o[5], o[6], o[7]);
        }
    }
}

// ---------------------------------------------------------------------------
// Launch
//   out layout per row (pitch 512):
//     [0:128)   self_out = relu(X@mlp_w1 + b1) @ mlp_w2 + b2
//     [128:384) h1       = relu((A@X) @ W1)
//     [384:512) h2       = A @ (h1 @ W2)      (associativity)
// ---------------------------------------------------------------------------
extern "C" void kernel_launch(void* const* d_in, const int* in_sizes, int n_in,
                              void* d_out, int out_size)
{
    const float* features = (const float*)d_in[0];
    const int*   esrc     = (const int*)  d_in[1];
    const int*   edst     = (const int*)  d_in[2];
    const float* ew       = (const float*)d_in[3];
    const float* W1       = (const float*)d_in[4];
    const float* W2       = (const float*)d_in[5];
    const float* mw1      = (const float*)d_in[6];
    const float* mb1      = (const float*)d_in[7];
    const float* mw2      = (const float*)d_in[8];
    const float* mb2      = (const float*)d_in[9];
    float* out = (float*)d_out;

    const int M = in_sizes[0] / IN_F;   // 50000
    const int E = in_sizes[1];          // 800000

    float *agg1, *S, *T;
    cudaGetSymbolAddress((void**)&agg1, g_agg1);
    cudaGetSymbolAddress((void**)&S,    g_S);
    cudaGetSymbolAddress((void**)&T,    g_T);

    const int LDOUT = OUT_F + HID_F + OUT_F;   // 512
    const dim3 blk(256);
    const int gm = (M + GBM - 1) / GBM;        // 391

    // 1. zero agg1 and out[:,384:512)
    {
        int total = M * 96;  // float4 count (64 + 32 per row)
        zero_kernel<<<(total + 255) / 256, blk>>>((float4*)agg1, (float4*)out, M);
    }

    // 2. agg1 = A @ X    (edge-parallel atomic scatter, 256 cols)
    {
        long long th = (long long)E * 64;
        spmm_kernel<64><<<(unsigned)((th + 255) / 256), blk>>>(
            features, esrc, edst, ew, E, agg1, HID_F);
    }

    // 3. h1 = relu(agg1 @ W1) -> out[:,128:384)
    sgemm_kernel<<<dim3(HID_F / GBN, gm), blk>>>(
        agg1, HID_F, W1, HID_F, out + OUT_F, LDOUT, nullptr, 1, M);

    // 4. S = relu(X @ mlp_w1 + b1)
    sgemm_kernel<<<dim3(HID_F / GBN, gm), blk>>>(
        features, IN_F, mw1, HID_F, S, HID_F, mb1, 1, M);

    // 5. self_out = S @ mlp_w2 + b2 -> out[:,0:128)
    sgemm_kernel<<<dim3(OUT_F / GBN, gm), blk>>>(
        S, HID_F, mw2, OUT_F, out, LDOUT, mb2, 0, M);

    // 6. T = h1 @ W2   (h1 read from out slab, pitch 512)
    sgemm_kernel<<<dim3(OUT_F / GBN, gm), blk>>>(
        out + OUT_F, LDOUT, W2, OUT_F, T, OUT_F, nullptr, 0, M);

    // 7. h2 = A @ T -> out[:,384:512)   (edge-parallel atomic scatter, 128 cols)
    {
        long long th = (long long)E * 32;
        spmm_kernel<32><<<(unsigned)((th + 255) / 256), blk>>>(
            T, esrc, edst, ew, E, out + OUT_F + HID_F, LDOUT);
    }
}

// round 6
// speedup vs baseline: 1.0966x; 1.0966x over previous
#include <cuda_runtime.h>
#include <cuda_bf16.h>
#include <cstdint>

// Problem constants (fixed by the dataset)
#define NNODES 50000
#define IN_F   256
#define HID_F  256
#define OUT_F  128
// out row pitch = OUT_F + HID_F + OUT_F = 512

typedef unsigned long long u64;

// ---------------------------------------------------------------------------
// Scratch (no cudaMalloc allowed): device globals.
// ---------------------------------------------------------------------------
__device__ float g_agg1[(size_t)NNODES * HID_F];
__device__ float g_S   [(size_t)NNODES * HID_F];
__device__ float g_T   [(size_t)NNODES * OUT_F];

// ---------------------------------------------------------------------------
// Zero-init: g_agg1 (N*256 floats) and out[:, 384:512) (N*128 floats)
// ---------------------------------------------------------------------------
__global__ __launch_bounds__(256) void zero_kernel(float4* __restrict__ agg1,
                                                   float4* __restrict__ out,
                                                   int n)
{
    int idx = blockIdx.x * blockDim.x + threadIdx.x;
    int total1 = n * 64;              // N*256 floats = N*64 float4
    if (idx < total1) {
        agg1[idx] = make_float4(0.f, 0.f, 0.f, 0.f);
    } else {
        int t = idx - total1;
        if (t < n * 32) {             // N*128 floats = N*32 float4
            int row = t >> 5;
            int c   = t & 31;
            out[(size_t)row * 128 + 96 + c] = make_float4(0.f, 0.f, 0.f, 0.f);
        }
    }
}

// ---------------------------------------------------------------------------
// Edge-parallel SpMM: out[dst] += w * x[src]  via red.global.add.v4.f32
// ---------------------------------------------------------------------------
template <int C4>
__global__ __launch_bounds__(256) void spmm_kernel(
    const float* __restrict__ x,
    const int*   __restrict__ src,
    const int*   __restrict__ dst,
    const float* __restrict__ w,
    int nE,
    float* __restrict__ out, int opitch)
{
    int idx = blockIdx.x * blockDim.x + threadIdx.x;
    int e = idx / C4;
    int c = idx % C4;
    if (e >= nE) return;

    int   s  = __ldg(src + e);
    int   d  = __ldg(dst + e);
    float ww = __ldg(w + e);

    float4 v = __ldg(reinterpret_cast<const float4*>(x) + (size_t)s * C4 + c);

    float* o = out + (size_t)d * opitch + c * 4;
    asm volatile("red.global.add.v4.f32 [%0], {%1, %2, %3, %4};"
                 :: "l"(o), "f"(v.x * ww), "f"(v.y * ww),
                    "f"(v.z * ww), "f"(v.w * ww)
                 : "memory");
}

// ---------------------------------------------------------------------------
// FP32 SGEMM with packed fma.rn.f32x2 (SASS FFMA2): doubles the fp32 FMA
// rate vs FFMA-3reg (rt_SMSP=2 issue ceiling we measured at 36 TF/s).
//   C[M, Ncols] = act( A[M, 256] @ B[256, Ncols] + bias )
//   BM=128, BN=128, BK=16, 256 threads.
//   Per thread: 8 rows x 4 column-PAIRS (f32x2 accumulators).
// ---------------------------------------------------------------------------
#define GEMM_K 256
#define GBM 128
#define GBN 128
#define GBK 16

// Packed fp32 pair FMA: d = a*b + d (lanewise). No volatile: let ptxas schedule.
#define FFMA2(d, a, b) \
    asm("fma.rn.f32x2 %0, %1, %2, %0;" : "+l"(d) : "l"(a), "l"(b))

__device__ __forceinline__ u64 dup_f32x2(float x) {
    u64 r;
    unsigned u = __float_as_uint(x);
    asm("mov.b64 %0, {%1, %1};" : "=l"(r) : "r"(u));
    return r;
}

__device__ __forceinline__ float2 unpack_f32x2(u64 v) {
    unsigned lo, hi;
    asm("mov.b64 {%0, %1}, %2;" : "=r"(lo), "=r"(hi) : "l"(v));
    return make_float2(__uint_as_float(lo), __uint_as_float(hi));
}

__global__ __launch_bounds__(256, 2) void sgemm_kernel(
    const float* __restrict__ A, int lda,
    const float* __restrict__ B, int ldb,
    float* __restrict__ C, int ldc,
    const float* __restrict__ bias, int do_relu, int M)
{
    __shared__ float As[GBK][GBM];
    __shared__ float Bs[GBK][GBN];

    const int tid = threadIdx.x;
    const int tr  = tid >> 4;   // 0..15  (row group)
    const int tc  = tid & 15;   // 0..15  (col-pair group: cols tc*8..tc*8+7)
    const int mBase = blockIdx.y * GBM;
    const int nBase = blockIdx.x * GBN;

    // 8 rows x 4 f32x2 column pairs
    u64 acc[8][4];
#pragma unroll
    for (int i = 0; i < 8; ++i)
#pragma unroll
        for (int j = 0; j < 4; ++j) acc[i][j] = 0ULL;

    // A loader: 512 float4 per tile, 2 per thread (transpose into As[k][m]).
    const int arow0 = tid >> 2;   // 0..63
    const int akq   = tid & 3;
    // B loader: 512 float4 per tile, 2 per thread.
    const int bk0 = tid >> 5;     // 0..7
    const int bn4 = tid & 31;     // 0..31

    for (int k0 = 0; k0 < GEMM_K; k0 += GBK) {
#pragma unroll
        for (int h = 0; h < 2; ++h) {
            int row = arow0 + h * 64;
            int gm  = mBase + row;
            float4 v = make_float4(0.f, 0.f, 0.f, 0.f);
            if (gm < M)
                v = __ldg(reinterpret_cast<const float4*>(
                        A + (size_t)gm * lda + k0 + akq * 4));
            As[akq * 4 + 0][row] = v.x;
            As[akq * 4 + 1][row] = v.y;
            As[akq * 4 + 2][row] = v.z;
            As[akq * 4 + 3][row] = v.w;
        }
#pragma unroll
        for (int h = 0; h < 2; ++h) {
            int kr = bk0 + h * 8;
            float4 v = __ldg(reinterpret_cast<const float4*>(
                    B + (size_t)(k0 + kr) * ldb + nBase + bn4 * 4));
            *reinterpret_cast<float4*>(&Bs[kr][bn4 * 4]) = v;
        }
        __syncthreads();

#pragma unroll
        for (int kk = 0; kk < GBK; ++kk) {
            float4 a0 = *reinterpret_cast<const float4*>(&As[kk][tr * 8]);
            float4 a1 = *reinterpret_cast<const float4*>(&As[kk][tr * 8 + 4]);
            // B column pairs come packed straight out of shared memory.
            ulonglong2 bp0 = *reinterpret_cast<const ulonglong2*>(&Bs[kk][tc * 8]);
            ulonglong2 bp1 = *reinterpret_cast<const ulonglong2*>(&Bs[kk][tc * 8 + 4]);
            u64 b[4] = {bp0.x, bp0.y, bp1.x, bp1.y};
            float av[8] = {a0.x, a0.y, a0.z, a0.w, a1.x, a1.y, a1.z, a1.w};
#pragma unroll
            for (int i = 0; i < 8; ++i) {
                u64 ad = dup_f32x2(av[i]);   // broadcast a into both lanes
                // keep 'ad' constant across 4 consecutive FFMA2s (reuse cache)
#pragma unroll
                for (int j = 0; j < 4; ++j)
                    FFMA2(acc[i][j], ad, b[j]);
            }
        }
        __syncthreads();
    }

    // Epilogue
    float bv[8];
#pragma unroll
    for (int j = 0; j < 8; ++j)
        bv[j] = bias ? __ldg(bias + nBase + tc * 8 + j) : 0.f;

#pragma unroll
    for (int i = 0; i < 8; ++i) {
        int gm = mBase + tr * 8 + i;
        if (gm < M) {
            float o[8];
#pragma unroll
            for (int jp = 0; jp < 4; ++jp) {
                float2 p = unpack_f32x2(acc[i][jp]);
                float v0 = p.x + bv[2 * jp];
                float v1 = p.y + bv[2 * jp + 1];
                if (do_relu) { v0 = fmaxf(v0, 0.f); v1 = fmaxf(v1, 0.f); }
                o[2 * jp]     = v0;
                o[2 * jp + 1] = v1;
            }
            float* cp = C + (size_t)gm * ldc + nBase + tc * 8;
            *reinterpret_cast<float4*>(cp)     = make_float4(o[0], o[1], o[2], o[3]);
            *reinterpret_cast<float4*>(cp + 4) = make_float4(o[4], o[5], o[6], o[7]);
        }
    }
}

// ---------------------------------------------------------------------------
// Launch
//   out layout per row (pitch 512):
//     [0:128)   self_out = relu(X@mlp_w1 + b1) @ mlp_w2 + b2
//     [128:384) h1       = relu((A@X) @ W1)
//     [384:512) h2       = A @ (h1 @ W2)      (associativity)
// ---------------------------------------------------------------------------
extern "C" void kernel_launch(void* const* d_in, const int* in_sizes, int n_in,
                              void* d_out, int out_size)
{
    const float* features = (const float*)d_in[0];
    const int*   esrc     = (const int*)  d_in[1];
    const int*   edst     = (const int*)  d_in[2];
    const float* ew       = (const float*)d_in[3];
    const float* W1       = (const float*)d_in[4];
    const float* W2       = (const float*)d_in[5];
    const float* mw1      = (const float*)d_in[6];
    const float* mb1      = (const float*)d_in[7];
    const float* mw2      = (const float*)d_in[8];
    const float* mb2      = (const float*)d_in[9];
    float* out = (float*)d_out;

    const int M = in_sizes[0] / IN_F;   // 50000
    const int E = in_sizes[1];          // 800000

    float *agg1, *S, *T;
    cudaGetSymbolAddress((void**)&agg1, g_agg1);
    cudaGetSymbolAddress((void**)&S,    g_S);
    cudaGetSymbolAddress((void**)&T,    g_T);

    const int LDOUT = OUT_F + HID_F + OUT_F;   // 512
    const dim3 blk(256);
    const int gm = (M + GBM - 1) / GBM;        // 391

    // 1. zero agg1 and out[:,384:512)
    {
        int total = M * 96;  // float4 count (64 + 32 per row)
        zero_kernel<<<(total + 255) / 256, blk>>>((float4*)agg1, (float4*)out, M);
    }

    // 2. agg1 = A @ X    (edge-parallel atomic scatter, 256 cols)
    {
        long long th = (long long)E * 64;
        spmm_kernel<64><<<(unsigned)((th + 255) / 256), blk>>>(
            features, esrc, edst, ew, E, agg1, HID_F);
    }

    // 3. h1 = relu(agg1 @ W1) -> out[:,128:384)
    sgemm_kernel<<<dim3(HID_F / GBN, gm), blk>>>(
        agg1, HID_F, W1, HID_F, out + OUT_F, LDOUT, nullptr, 1, M);

    // 4. S = relu(X @ mlp_w1 + b1)
    sgemm_kernel<<<dim3(HID_F / GBN, gm), blk>>>(
        features, IN_F, mw1, HID_F, S, HID_F, mb1, 1, M);

    // 5. self_out = S @ mlp_w2 + b2 -> out[:,0:128)
    sgemm_kernel<<<dim3(OUT_F / GBN, gm), blk>>>(
        S, HID_F, mw2, OUT_F, out, LDOUT, mb2, 0, M);

    // 6. T = h1 @ W2   (h1 read from out slab, pitch 512)
    sgemm_kernel<<<dim3(OUT_F / GBN, gm), blk>>>(
        out + OUT_F, LDOUT, W2, OUT_F, T, OUT_F, nullptr, 0, M);

    // 7. h2 = A @ T -> out[:,384:512)   (edge-parallel atomic scatter, 128 cols)
    {
        long long th = (long long)E * 32;
        spmm_kernel<32><<<(unsigned)((th + 255) / 256), blk>>>(
            T, esrc, edst, ew, E, out + OUT_F + HID_F, LDOUT);
    }
}

// round 7
// speedup vs baseline: 1.3720x; 1.2511x over previous
#include <cuda_runtime.h>
#include <cuda_bf16.h>
#include <cstdint>

// Problem constants (fixed by the dataset)
#define NNODES 50000
#define IN_F   256
#define HID_F  256
#define OUT_F  128
#define GK     256        // K is 256 for every GEMM in this problem
// out row pitch = OUT_F + HID_F + OUT_F = 512

typedef unsigned int uint;

// ---------------------------------------------------------------------------
// Scratch (no cudaMalloc allowed): device globals.
// ---------------------------------------------------------------------------
__device__ float g_agg1[(size_t)NNODES * HID_F];
__device__ float g_S   [(size_t)NNODES * HID_F];
__device__ float g_T   [(size_t)NNODES * OUT_F];

// Preconverted, transposed weights: Bt[n*GK + k], split into bf16 hi/lo.
__device__ __nv_bfloat16 g_W1t_hi [HID_F * GK];
__device__ __nv_bfloat16 g_W1t_lo [HID_F * GK];
__device__ __nv_bfloat16 g_mw1t_hi[HID_F * GK];
__device__ __nv_bfloat16 g_mw1t_lo[HID_F * GK];
__device__ __nv_bfloat16 g_mw2t_hi[OUT_F * GK];
__device__ __nv_bfloat16 g_mw2t_lo[OUT_F * GK];
__device__ __nv_bfloat16 g_W2t_hi [OUT_F * GK];
__device__ __nv_bfloat16 g_W2t_lo [OUT_F * GK];

// ---------------------------------------------------------------------------
// Zero-init: g_agg1 (N*256 floats) and out[:, 384:512) (N*128 floats)
// ---------------------------------------------------------------------------
__global__ __launch_bounds__(256) void zero_kernel(float4* __restrict__ agg1,
                                                   float4* __restrict__ out,
                                                   int n)
{
    int idx = blockIdx.x * blockDim.x + threadIdx.x;
    int total1 = n * 64;
    if (idx < total1) {
        agg1[idx] = make_float4(0.f, 0.f, 0.f, 0.f);
    } else {
        int t = idx - total1;
        if (t < n * 32) {
            int row = t >> 5;
            int c   = t & 31;
            out[(size_t)row * 128 + 96 + c] = make_float4(0.f, 0.f, 0.f, 0.f);
        }
    }
}

// ---------------------------------------------------------------------------
// Weight preconvert: B[k][n] fp32 -> Bt_hi/Bt_lo[n][k] bf16 (split).
// ---------------------------------------------------------------------------
__global__ __launch_bounds__(256) void convB_kernel(
    const float* __restrict__ B, int Ncols,
    __nv_bfloat16* __restrict__ Bt_hi, __nv_bfloat16* __restrict__ Bt_lo)
{
    int idx = blockIdx.x * blockDim.x + threadIdx.x;
    if (idx >= GK * Ncols) return;
    int k = idx / Ncols;
    int n = idx % Ncols;
    float x = B[idx];
    __nv_bfloat16 h = __float2bfloat16(x);
    float r = x - __bfloat162float(h);
    Bt_hi[(size_t)n * GK + k] = h;
    Bt_lo[(size_t)n * GK + k] = __float2bfloat16(r);
}

// ---------------------------------------------------------------------------
// Edge-parallel SpMM: out[dst] += w * x[src]  via red.global.add.v4.f32
// ---------------------------------------------------------------------------
template <int C4>
__global__ __launch_bounds__(256) void spmm_kernel(
    const float* __restrict__ x,
    const int*   __restrict__ src,
    const int*   __restrict__ dst,
    const float* __restrict__ w,
    int nE,
    float* __restrict__ out, int opitch)
{
    int idx = blockIdx.x * blockDim.x + threadIdx.x;
    int e = idx / C4;
    int c = idx % C4;
    if (e >= nE) return;

    int   s  = __ldg(src + e);
    int   d  = __ldg(dst + e);
    float ww = __ldg(w + e);

    float4 v = __ldg(reinterpret_cast<const float4*>(x) + (size_t)s * C4 + c);

    float* o = out + (size_t)d * opitch + c * 4;
    asm volatile("red.global.add.v4.f32 [%0], {%1, %2, %3, %4};"
                 :: "l"(o), "f"(v.x * ww), "f"(v.y * ww),
                    "f"(v.z * ww), "f"(v.w * ww)
                 : "memory");
}

// ---------------------------------------------------------------------------
// Split-bf16 tensor-core GEMM:
//   C[M, Ncols] = act( A[M, 256] @ B[256, Ncols] + bias )
// A fp32, split on the fly. B preconverted (transposed bf16 hi/lo).
// 3-term compensation: Ahi*Bhi + Alo*Bhi + Ahi*Blo  (error ~2^-18).
// Block 128x128, BK=32, 256 threads = 8 warps, warp tile 64x32,
// mma.sync.m16n8k16.
// ---------------------------------------------------------------------------
#define TBM 128
#define TBN 128
#define TBK 32
#define SAK 40          // padded k-stride (bf16 elems): conflict-free frags

#define MMA_BF16(c0,c1,c2,c3, a0,a1,a2,a3, b0,b1)                          \
    asm("mma.sync.aligned.m16n8k16.row.col.f32.bf16.bf16.f32 "             \
        "{%0,%1,%2,%3}, {%4,%5,%6,%7}, {%8,%9}, {%0,%1,%2,%3};"            \
        : "+f"(c0), "+f"(c1), "+f"(c2), "+f"(c3)                            \
        : "r"(a0), "r"(a1), "r"(a2), "r"(a3), "r"(b0), "r"(b1))

__global__ __launch_bounds__(256, 2) void bgemm_kernel(
    const float* __restrict__ A, int lda,
    const __nv_bfloat16* __restrict__ Bt_hi,
    const __nv_bfloat16* __restrict__ Bt_lo,
    float* __restrict__ C, int ldc,
    const float* __restrict__ bias, int do_relu, int M)
{
    __shared__ __nv_bfloat16 sAhi[TBM * SAK];
    __shared__ __nv_bfloat16 sAlo[TBM * SAK];
    __shared__ __nv_bfloat16 sBhi[TBN * SAK];
    __shared__ __nv_bfloat16 sBlo[TBN * SAK];

    const int tid   = threadIdx.x;
    const int lane  = tid & 31;
    const int warp  = tid >> 5;
    const int gid   = lane >> 2;    // 0..7
    const int tig   = lane & 3;     // 0..3
    const int wm    = warp & 1;     // 2 warp-rows  (64 m each)
    const int wn    = warp >> 1;    // 4 warp-cols  (32 n each)
    const int mBase = blockIdx.y * TBM;
    const int nBase = blockIdx.x * TBN;

    float acc[4][4][4];
#pragma unroll
    for (int i = 0; i < 4; ++i)
#pragma unroll
        for (int j = 0; j < 4; ++j)
#pragma unroll
            for (int q = 0; q < 4; ++q) acc[i][j][q] = 0.f;

    // A loader mapping: 2 threads per row, 4 float4 each (32 floats/row)
    const int am = tid >> 1;        // 0..127
    const int ah = tid & 1;         // 0/1 (which 16-col half)
    // B loader mapping: 2 threads per row of 32 bf16 (64B)
    const int bn = tid & 127;       // 0..127
    const int bp = tid >> 7;        // 0/1 (which 16-elem half)

    const bool a_valid = (mBase + am) < M;
    const float* aptr = A + (size_t)(mBase + am) * lda + ah * 16;

    for (int k0 = 0; k0 < GK; k0 += TBK) {
        // ---- load + split A tile ----
#pragma unroll
        for (int j = 0; j < 4; ++j) {
            float4 v = make_float4(0.f, 0.f, 0.f, 0.f);
            if (a_valid)
                v = __ldg(reinterpret_cast<const float4*>(aptr + k0) + j);
            int kk = ah * 16 + j * 4;
            __nv_bfloat162 h0, h1, l0, l1;
            h0.x = __float2bfloat16(v.x);
            h0.y = __float2bfloat16(v.y);
            h1.x = __float2bfloat16(v.z);
            h1.y = __float2bfloat16(v.w);
            l0.x = __float2bfloat16(v.x - __bfloat162float(h0.x));
            l0.y = __float2bfloat16(v.y - __bfloat162float(h0.y));
            l1.x = __float2bfloat16(v.z - __bfloat162float(h1.x));
            l1.y = __float2bfloat16(v.w - __bfloat162float(h1.y));
            *reinterpret_cast<__nv_bfloat162*>(&sAhi[am * SAK + kk])     = h0;
            *reinterpret_cast<__nv_bfloat162*>(&sAhi[am * SAK + kk + 2]) = h1;
            *reinterpret_cast<__nv_bfloat162*>(&sAlo[am * SAK + kk])     = l0;
            *reinterpret_cast<__nv_bfloat162*>(&sAlo[am * SAK + kk + 2]) = l1;
        }
        // ---- load B tile (already bf16 hi/lo, [n][k]) ----
        {
            const uint4* sh = reinterpret_cast<const uint4*>(
                Bt_hi + (size_t)(nBase + bn) * GK + k0) + bp * 2;
            const uint4* sl = reinterpret_cast<const uint4*>(
                Bt_lo + (size_t)(nBase + bn) * GK + k0) + bp * 2;
            uint4 h0 = __ldg(sh), h1 = __ldg(sh + 1);
            uint4 l0 = __ldg(sl), l1 = __ldg(sl + 1);
            uint4* dh = reinterpret_cast<uint4*>(&sBhi[bn * SAK + bp * 16]);
            uint4* dl = reinterpret_cast<uint4*>(&sBlo[bn * SAK + bp * 16]);
            dh[0] = h0; dh[1] = h1;
            dl[0] = l0; dl[1] = l1;
        }
        __syncthreads();

        // ---- two k16 steps ----
#pragma unroll
        for (int kb = 0; kb < TBK; kb += 16) {
            uint bh0[4], bh1[4], bl0[4], bl1[4];
#pragma unroll
            for (int ns = 0; ns < 4; ++ns) {
                int base = (wn * 32 + ns * 8 + gid) * SAK + kb + tig * 2;
                bh0[ns] = *reinterpret_cast<const uint*>(&sBhi[base]);
                bh1[ns] = *reinterpret_cast<const uint*>(&sBhi[base + 8]);
                bl0[ns] = *reinterpret_cast<const uint*>(&sBlo[base]);
                bl1[ns] = *reinterpret_cast<const uint*>(&sBlo[base + 8]);
            }
#pragma unroll
            for (int ms = 0; ms < 4; ++ms) {
                int base = (wm * 64 + ms * 16 + gid) * SAK + kb + tig * 2;
                uint ah0 = *reinterpret_cast<const uint*>(&sAhi[base]);
                uint ah1 = *reinterpret_cast<const uint*>(&sAhi[base + 8 * SAK]);
                uint ah2 = *reinterpret_cast<const uint*>(&sAhi[base + 8]);
                uint ah3 = *reinterpret_cast<const uint*>(&sAhi[base + 8 * SAK + 8]);
                uint al0 = *reinterpret_cast<const uint*>(&sAlo[base]);
                uint al1 = *reinterpret_cast<const uint*>(&sAlo[base + 8 * SAK]);
                uint al2 = *reinterpret_cast<const uint*>(&sAlo[base + 8]);
                uint al3 = *reinterpret_cast<const uint*>(&sAlo[base + 8 * SAK + 8]);
#pragma unroll
                for (int ns = 0; ns < 4; ++ns) {
                    float* c = acc[ms][ns];
                    MMA_BF16(c[0], c[1], c[2], c[3],
                             ah0, ah1, ah2, ah3, bh0[ns], bh1[ns]);
                    MMA_BF16(c[0], c[1], c[2], c[3],
                             al0, al1, al2, al3, bh0[ns], bh1[ns]);
                    MMA_BF16(c[0], c[1], c[2], c[3],
                             ah0, ah1, ah2, ah3, bl0[ns], bl1[ns]);
                }
            }
        }
        __syncthreads();
    }

    // ---- epilogue ----
#pragma unroll
    for (int ns = 0; ns < 4; ++ns) {
        int col = nBase + wn * 32 + ns * 8 + tig * 2;
        float b0 = bias ? __ldg(bias + col)     : 0.f;
        float b1 = bias ? __ldg(bias + col + 1) : 0.f;
#pragma unroll
        for (int ms = 0; ms < 4; ++ms) {
            int row = mBase + wm * 64 + ms * 16 + gid;
            float v0 = acc[ms][ns][0] + b0;
            float v1 = acc[ms][ns][1] + b1;
            float v2 = acc[ms][ns][2] + b0;
            float v3 = acc[ms][ns][3] + b1;
            if (do_relu) {
                v0 = fmaxf(v0, 0.f); v1 = fmaxf(v1, 0.f);
                v2 = fmaxf(v2, 0.f); v3 = fmaxf(v3, 0.f);
            }
            if (row < M)
                *reinterpret_cast<float2*>(C + (size_t)row * ldc + col) =
                    make_float2(v0, v1);
            if (row + 8 < M)
                *reinterpret_cast<float2*>(C + (size_t)(row + 8) * ldc + col) =
                    make_float2(v2, v3);
        }
    }
}

// ---------------------------------------------------------------------------
// Launch
//   out layout per row (pitch 512):
//     [0:128)   self_out = relu(X@mlp_w1 + b1) @ mlp_w2 + b2
//     [128:384) h1       = relu((A@X) @ W1)
//     [384:512) h2       = A @ (h1 @ W2)      (associativity)
// ---------------------------------------------------------------------------
extern "C" void kernel_launch(void* const* d_in, const int* in_sizes, int n_in,
                              void* d_out, int out_size)
{
    const float* features = (const float*)d_in[0];
    const int*   esrc     = (const int*)  d_in[1];
    const int*   edst     = (const int*)  d_in[2];
    const float* ew       = (const float*)d_in[3];
    const float* W1       = (const float*)d_in[4];
    const float* W2       = (const float*)d_in[5];
    const float* mw1      = (const float*)d_in[6];
    const float* mb1      = (const float*)d_in[7];
    const float* mw2      = (const float*)d_in[8];
    const float* mb2      = (const float*)d_in[9];
    float* out = (float*)d_out;

    const int M = in_sizes[0] / IN_F;   // 50000
    const int E = in_sizes[1];          // 800000

    float *agg1, *S, *T;
    cudaGetSymbolAddress((void**)&agg1, g_agg1);
    cudaGetSymbolAddress((void**)&S,    g_S);
    cudaGetSymbolAddress((void**)&T,    g_T);

    __nv_bfloat16 *W1h, *W1l, *m1h, *m1l, *m2h, *m2l, *W2h, *W2l;
    cudaGetSymbolAddress((void**)&W1h, g_W1t_hi);
    cudaGetSymbolAddress((void**)&W1l, g_W1t_lo);
    cudaGetSymbolAddress((void**)&m1h, g_mw1t_hi);
    cudaGetSymbolAddress((void**)&m1l, g_mw1t_lo);
    cudaGetSymbolAddress((void**)&m2h, g_mw2t_hi);
    cudaGetSymbolAddress((void**)&m2l, g_mw2t_lo);
    cudaGetSymbolAddress((void**)&W2h, g_W2t_hi);
    cudaGetSymbolAddress((void**)&W2l, g_W2t_lo);

    const int LDOUT = OUT_F + HID_F + OUT_F;   // 512
    const dim3 blk(256);
    const int gm = (M + TBM - 1) / TBM;        // 391

    // 0. preconvert weights (transposed bf16 hi/lo)
    convB_kernel<<<(GK * HID_F + 255) / 256, blk>>>(W1,  HID_F, W1h, W1l);
    convB_kernel<<<(GK * HID_F + 255) / 256, blk>>>(mw1, HID_F, m1h, m1l);
    convB_kernel<<<(GK * OUT_F + 255) / 256, blk>>>(mw2, OUT_F, m2h, m2l);
    convB_kernel<<<(GK * OUT_F + 255) / 256, blk>>>(W2,  OUT_F, W2h, W2l);

    // 1. zero agg1 and out[:,384:512)
    {
        int total = M * 96;
        zero_kernel<<<(total + 255) / 256, blk>>>((float4*)agg1, (float4*)out, M);
    }

    // 2. agg1 = A @ X    (edge-parallel atomic scatter, 256 cols)
    {
        long long th = (long long)E * 64;
        spmm_kernel<64><<<(unsigned)((th + 255) / 256), blk>>>(
            features, esrc, edst, ew, E, agg1, HID_F);
    }

    // 3. h1 = relu(agg1 @ W1) -> out[:,128:384)
    bgemm_kernel<<<dim3(HID_F / TBN, gm), blk>>>(
        agg1, HID_F, W1h, W1l, out + OUT_F, LDOUT, nullptr, 1, M);

    // 4. S = relu(X @ mlp_w1 + b1)
    bgemm_kernel<<<dim3(HID_F / TBN, gm), blk>>>(
        features, IN_F, m1h, m1l, S, HID_F, mb1, 1, M);

    // 5. self_out = S @ mlp_w2 + b2 -> out[:,0:128)
    bgemm_kernel<<<dim3(OUT_F / TBN, gm), blk>>>(
        S, HID_F, m2h, m2l, out, LDOUT, mb2, 0, M);

    // 6. T = h1 @ W2   (h1 read from out slab, pitch 512)
    bgemm_kernel<<<dim3(OUT_F / TBN, gm), blk>>>(
        out + OUT_F, LDOUT, W2h, W2l, T, OUT_F, nullptr, 0, M);

    // 7. h2 = A @ T -> out[:,384:512)   (edge-parallel atomic scatter)
    {
        long long th = (long long)E * 32;
        spmm_kernel<32><<<(unsigned)((th + 255) / 256), blk>>>(
            T, esrc, edst, ew, E, out + OUT_F + HID_F, LDOUT);
    }
}